// round 10
// baseline (speedup 1.0000x reference)
#include <cuda_runtime.h>
#include <cuda_bf16.h>
#include <cstdint>

#define HDIM 128
#define MH 64
#define MAXB 2048
#define CHUNK 1024
#define ROWS_PER_WARP 128
#define LN_EPS 1e-5f

// ---------------- scratch (static device globals; zero-initialized) -------
// ZERO is the identity everywhere (min kept as max of negated keys); the MLP
// tail zeroes each graph's slice after reading, and the exit ticket resets
// the barrier counters, so every graph replay sees identity state.
__device__ float    g_sum [MAXB * HDIM];
__device__ float    g_sq  [MAXB * HDIM];
__device__ unsigned g_minb[MAXB * HDIM];   // max of fkey(-v)
__device__ unsigned g_maxb[MAXB * HDIM];   // max of fkey(v)
__device__ float    g_cnt [MAXB];
__device__ int      g_arrive;
__device__ int      g_exit;

__device__ __forceinline__ unsigned fkey(float f) {
    unsigned b = __float_as_uint(f);
    return (b & 0x80000000u) ? ~b : (b | 0x80000000u);
}
__device__ __forceinline__ float funkey(unsigned k) {
    return __uint_as_float((k & 0x80000000u) ? (k ^ 0x80000000u) : ~k);
}

struct Acc4 {
    float4 s, q, mn, mx;
    int cnt;
};
__device__ __forceinline__ void acc_reset(Acc4& a, const float4& v) {
    a.s = v;
    a.q = make_float4(v.x * v.x, v.y * v.y, v.z * v.z, v.w * v.w);
    a.mn = v; a.mx = v; a.cnt = 1;
}
__device__ __forceinline__ void acc_add(Acc4& a, const float4& v) {
    a.s.x += v.x; a.s.y += v.y; a.s.z += v.z; a.s.w += v.w;
    a.q.x = fmaf(v.x, v.x, a.q.x); a.q.y = fmaf(v.y, v.y, a.q.y);
    a.q.z = fmaf(v.z, v.z, a.q.z); a.q.w = fmaf(v.w, v.w, a.q.w);
    a.mn.x = fminf(a.mn.x, v.x); a.mn.y = fminf(a.mn.y, v.y);
    a.mn.z = fminf(a.mn.z, v.z); a.mn.w = fminf(a.mn.w, v.w);
    a.mx.x = fmaxf(a.mx.x, v.x); a.mx.y = fmaxf(a.mx.y, v.y);
    a.mx.z = fmaxf(a.mx.z, v.z); a.mx.w = fmaxf(a.mx.w, v.w);
}
__device__ __forceinline__ void acc_flush(const Acc4& a, int seg, int colbase, int lane) {
    int o = seg * HDIM + colbase;
    atomicAdd(&g_sum[o + 0], a.s.x); atomicAdd(&g_sum[o + 1], a.s.y);
    atomicAdd(&g_sum[o + 2], a.s.z); atomicAdd(&g_sum[o + 3], a.s.w);
    atomicAdd(&g_sq[o + 0], a.q.x);  atomicAdd(&g_sq[o + 1], a.q.y);
    atomicAdd(&g_sq[o + 2], a.q.z);  atomicAdd(&g_sq[o + 3], a.q.w);
    atomicMax(&g_minb[o + 0], fkey(-a.mn.x)); atomicMax(&g_minb[o + 1], fkey(-a.mn.y));
    atomicMax(&g_minb[o + 2], fkey(-a.mn.z)); atomicMax(&g_minb[o + 3], fkey(-a.mn.w));
    atomicMax(&g_maxb[o + 0], fkey(a.mx.x));  atomicMax(&g_maxb[o + 1], fkey(a.mx.y));
    atomicMax(&g_maxb[o + 2], fkey(a.mx.z));  atomicMax(&g_maxb[o + 3], fkey(a.mx.w));
    if (lane == 0) atomicAdd(&g_cnt[seg], (float)a.cnt);
}

// smem union: phase-1 segment buffer overlays the MLP staging buffers
struct MlpS {
    float concat[2][5 * HDIM];   // 5 KB
    float part0[16][2][MH];      // 8 KB
    float part1[4][2][MH];       // 2 KB
    float part3[2][2][HDIM];     // 2 KB
    float h0[2][MH];
    float hb[2][MH];
};
union SmemU {
    int sb[CHUNK];
    MlpS m;
};

__global__ void __launch_bounds__(256, 4) fused_kernel(
    const float4* __restrict__ x4, const int* __restrict__ batch,
    int N, int nChunks, int NB,
    const float* __restrict__ u,
    const float* __restrict__ W0, const float* __restrict__ b0,
    const float* __restrict__ W1, const float* __restrict__ b1,
    const float* __restrict__ W2, const float* __restrict__ b2,
    const float* __restrict__ lng, const float* __restrict__ lnb,
    const float* __restrict__ W3, const float* __restrict__ b3,
    float* __restrict__ out, int B) {
    __shared__ SmemU s;
    const int t = threadIdx.x;
    const int warp = t >> 5;
    const int lane = t & 31;

    // ================= phase 1: chunks strided over persistent blocks ======
    for (int chunk = blockIdx.x; chunk < nChunks; chunk += NB) {
        const long long blockStart = (long long)chunk * CHUNK;
        const int rows = (int)min((long long)CHUNK, (long long)N - blockStart);

        for (int i = t; i < rows; i += 256) s.sb[i] = batch[blockStart + i];
        __syncthreads();

        const int wstart = warp * ROWS_PER_WARP;
        if (wstart < rows) {
            const int wend = min(wstart + ROWS_PER_WARP, rows);
            const float4* xp = x4 + (blockStart + wstart) * (HDIM / 4) + lane;

            Acc4 a;
            int cur = s.sb[wstart];
            {
                float4 v0 = __ldcs(xp);
                acc_reset(a, v0);
                xp += HDIM / 4;
            }
            int i = wstart + 1;
            for (; i + 8 <= wend; i += 8) {
                float4 v[8];
#pragma unroll
                for (int j = 0; j < 8; ++j) v[j] = __ldcs(xp + j * (HDIM / 4));
                if (s.sb[i + 7] == cur) {
#pragma unroll
                    for (int j = 0; j < 8; ++j) acc_add(a, v[j]);
                    a.cnt += 8;
                } else {
#pragma unroll
                    for (int j = 0; j < 8; ++j) {
                        int sg = s.sb[i + j];
                        if (sg != cur) {
                            acc_flush(a, cur, lane * 4, lane);
                            cur = sg;
                            acc_reset(a, v[j]);
                        } else {
                            acc_add(a, v[j]);
                            a.cnt++;
                        }
                    }
                }
                xp += 8 * (HDIM / 4);
            }
            for (; i < wend; ++i) {
                float4 v = __ldcs(xp);
                int sg = s.sb[i];
                if (sg != cur) {
                    acc_flush(a, cur, lane * 4, lane);
                    cur = sg;
                    acc_reset(a, v);
                } else {
                    acc_add(a, v);
                    a.cnt++;
                }
                xp += HDIM / 4;
            }
            acc_flush(a, cur, lane * 4, lane);
        }
        __syncthreads();   // protect s.sb before next chunk load
    }

    // ================= grid-wide barrier (all NB blocks co-resident) =======
    __threadfence();
    __syncthreads();
    if (t == 0) {
        atomicAdd(&g_arrive, 1);
        while (*(volatile int*)&g_arrive < NB) { __nanosleep(64); }
    }
    __syncthreads();
    __threadfence();

    // ================= MLP tail: 2 graphs per block =========================
    const int PAIRS = (B + 1) / 2;
    for (int p = blockIdx.x; p < PAIRS; p += NB) {
        const int g0 = p * 2;
        const int g1 = (p * 2 + 1 < B) ? p * 2 + 1 : p * 2;

        // ---- build concat = [u, s, min, max, var] for both graphs ----
        for (int idx = t; idx < 2 * 5 * HDIM; idx += 256) {
            int g = idx / (5 * HDIM);
            int j = idx - g * (5 * HDIM);
            int gid = g ? g1 : g0;
            int o = gid * HDIM + (j & (HDIM - 1));
            int sec = j >> 7;
            float val;
            if (sec == 0) {
                val = u[o];
            } else if (sec == 1) {
                val = g_sum[o];
            } else if (sec == 2) {
                val = -funkey(g_minb[o]);
            } else if (sec == 3) {
                val = funkey(g_maxb[o]);
            } else {
                float cv = fmaxf(g_cnt[gid], 1.0f);
                float me = g_sum[o] / cv;
                val = g_sq[o] / cv - me * me;
            }
            s.m.concat[g][j] = val;
        }
        __syncthreads();

        // ---- layer 0: 640 -> 64; 16-way K-split, 4 out x 2 graphs ----
        {
            const int mg = (t & 15) * 4;
            const int q  = t >> 4;
            float a00 = 0.f, a01 = 0.f, a02 = 0.f, a03 = 0.f;
            float a10 = 0.f, a11 = 0.f, a12 = 0.f, a13 = 0.f;
            const int k0 = q * 40;
#pragma unroll 8
            for (int k = k0; k < k0 + 40; ++k) {
                float4 w = *(const float4*)&W0[k * MH + mg];
                float c0 = s.m.concat[0][k];
                float c1 = s.m.concat[1][k];
                a00 = fmaf(c0, w.x, a00); a01 = fmaf(c0, w.y, a01);
                a02 = fmaf(c0, w.z, a02); a03 = fmaf(c0, w.w, a03);
                a10 = fmaf(c1, w.x, a10); a11 = fmaf(c1, w.y, a11);
                a12 = fmaf(c1, w.z, a12); a13 = fmaf(c1, w.w, a13);
            }
            s.m.part0[q][0][mg + 0] = a00; s.m.part0[q][0][mg + 1] = a01;
            s.m.part0[q][0][mg + 2] = a02; s.m.part0[q][0][mg + 3] = a03;
            s.m.part0[q][1][mg + 0] = a10; s.m.part0[q][1][mg + 1] = a11;
            s.m.part0[q][1][mg + 2] = a12; s.m.part0[q][1][mg + 3] = a13;
        }
        __syncthreads();
        if (t < 2 * MH) {
            int g = t >> 6, m = t & 63;
            float sum = 0.f;
#pragma unroll
            for (int q = 0; q < 16; ++q) sum += s.m.part0[q][g][m];
            s.m.h0[g][m] = fmaxf(sum + b0[m], 0.f);
        }
        __syncthreads();

        // ---- layer 1: 64 -> 64; 4-way K-split x 2 graphs ----
        {
            const int m = t & 63;
            const int q = t >> 6;
            float ac0 = 0.f, ac1 = 0.f;
            const int k0 = q * 16;
#pragma unroll
            for (int k = k0; k < k0 + 16; ++k) {
                float w = __ldg(&W1[k * MH + m]);
                ac0 = fmaf(s.m.h0[0][k], w, ac0);
                ac1 = fmaf(s.m.h0[1][k], w, ac1);
            }
            s.m.part1[q][0][m] = ac0;
            s.m.part1[q][1][m] = ac1;
        }
        __syncthreads();
        if (t < 2 * MH) {
            int g = t >> 6, m = t & 63;
            s.m.hb[g][m] = fmaxf(s.m.part1[0][g][m] + s.m.part1[1][g][m] +
                                 s.m.part1[2][g][m] + s.m.part1[3][g][m] + b1[m], 0.f);
        }
        __syncthreads();

        // ---- layer 2: 64 -> 64; 4-way K-split x 2 graphs ----
        {
            const int m = t & 63;
            const int q = t >> 6;
            float ac0 = 0.f, ac1 = 0.f;
            const int k0 = q * 16;
#pragma unroll
            for (int k = k0; k < k0 + 16; ++k) {
                float w = __ldg(&W2[k * MH + m]);
                ac0 = fmaf(s.m.hb[0][k], w, ac0);
                ac1 = fmaf(s.m.hb[1][k], w, ac1);
            }
            s.m.part1[q][0][m] = ac0;
            s.m.part1[q][1][m] = ac1;
        }
        __syncthreads();
        if (t < 2 * MH) {
            int g = t >> 6, m = t & 63;
            s.m.h0[g][m] = fmaxf(s.m.part1[0][g][m] + s.m.part1[1][g][m] +
                                 s.m.part1[2][g][m] + s.m.part1[3][g][m] + b2[m], 0.f);
        }
        __syncthreads();

        // ---- layernorm: warp g handles graph g ----
        if (t < 64) {
            const int g = t >> 5;
            const int l = t & 31;
            float v0 = s.m.h0[g][l], v1 = s.m.h0[g][l + 32];
            float sum = v0 + v1;
#pragma unroll
            for (int o = 16; o > 0; o >>= 1) sum += __shfl_xor_sync(0xFFFFFFFF, sum, o);
            float mu = sum * (1.0f / MH);
            float d0 = v0 - mu, d1 = v1 - mu;
            float vs = d0 * d0 + d1 * d1;
#pragma unroll
            for (int o = 16; o > 0; o >>= 1) vs += __shfl_xor_sync(0xFFFFFFFF, vs, o);
            float rstd = rsqrtf(vs * (1.0f / MH) + LN_EPS);
            s.m.hb[g][l]      = d0 * rstd * lng[l]      + lnb[l];
            s.m.hb[g][l + 32] = d1 * rstd * lng[l + 32] + lnb[l + 32];
        }
        __syncthreads();

        // ---- output layer: 64 -> 128; 2-way K-split x 2 graphs ----
        {
            const int col = t & 127;
            const int hf  = t >> 7;
            float ac0 = 0.f, ac1 = 0.f;
            const int k0 = hf * 32;
#pragma unroll 8
            for (int k = k0; k < k0 + 32; ++k) {
                float w = __ldg(&W3[k * HDIM + col]);
                ac0 = fmaf(s.m.hb[0][k], w, ac0);
                ac1 = fmaf(s.m.hb[1][k], w, ac1);
            }
            s.m.part3[hf][0][col] = ac0;
            s.m.part3[hf][1][col] = ac1;
        }
        __syncthreads();
        {
            const int g = t >> 7;
            const int col = t & 127;
            const int gid = g ? g1 : g0;
            int o = gid * HDIM + col;
            out[o] = u[o] + b3[col] + s.m.part3[0][g][col] + s.m.part3[1][g][col];

            // reset scratch slice to zero-identity for next replay
            g_sum[o] = 0.f;
            g_sq[o] = 0.f;
            g_minb[o] = 0u;
            g_maxb[o] = 0u;
            if (col == 0) g_cnt[gid] = 0.f;
        }
        __syncthreads();   // protect smem before next pair iteration
    }

    // ================= exit ticket: last block resets barrier counters =====
    __threadfence();
    __syncthreads();
    if (t == 0) {
        int tk = atomicAdd(&g_exit, 1);
        if (tk == NB - 1) {
            g_arrive = 0;
            g_exit = 0;
            __threadfence();
        }
    }
}

// ---------------- launch ----------------
extern "C" void kernel_launch(void* const* d_in, const int* in_sizes, int n_in,
                              void* d_out, int out_size) {
    const float* x     = (const float*)d_in[0];
    // d_in[1] edge_index, d_in[2] edge_attr : unused by the forward
    const float* u     = (const float*)d_in[3];
    const int*   batch = (const int*)d_in[4];
    const float* W0    = (const float*)d_in[5];
    const float* b0    = (const float*)d_in[6];
    const float* W1    = (const float*)d_in[7];
    const float* b1    = (const float*)d_in[8];
    const float* W2    = (const float*)d_in[9];
    const float* b2    = (const float*)d_in[10];
    const float* lng   = (const float*)d_in[11];
    const float* lnb   = (const float*)d_in[12];
    const float* W3    = (const float*)d_in[13];
    const float* b3    = (const float*)d_in[14];
    float* out = (float*)d_out;

    const int N = in_sizes[0] / HDIM;
    int B = in_sizes[3] / HDIM;
    if (B > MAXB) B = MAXB;

    static int smCount = 0;
    if (smCount == 0) {
        cudaDeviceGetAttribute(&smCount, cudaDevAttrMultiProcessorCount, 0);
        if (smCount <= 0) smCount = 148;
    }
    const int NB = smCount * 4;   // __launch_bounds__(256,4) guarantees residency
    const int nChunks = (N + CHUNK - 1) / CHUNK;

    fused_kernel<<<NB, 256>>>((const float4*)x, batch, N, nChunks, NB,
                              u, W0, b0, W1, b1, W2, b2, lng, lnb, W3, b3,
                              out, B);
}

// round 11
// speedup vs baseline: 1.0332x; 1.0332x over previous
#include <cuda_runtime.h>
#include <cuda_bf16.h>
#include <cstdint>

#define HDIM 128
#define MH 64
#define MAXB 2048
#define CHUNK 1024
#define ROWS_PER_PAIR 256
#define LN_EPS 1e-5f

// ---------------- scratch (static device globals; zero-initialized) -------
// ZERO is the identity everywhere (min kept as max of negated keys); the MLP
// tail zeroes each graph's slice after reading, and the exit ticket resets
// the barrier counters, so every graph replay sees identity state.
__device__ float    g_sum [MAXB * HDIM];
__device__ float    g_sq  [MAXB * HDIM];
__device__ unsigned g_minb[MAXB * HDIM];   // max of fkey(-v)
__device__ unsigned g_maxb[MAXB * HDIM];   // max of fkey(v)
__device__ float    g_cnt [MAXB];
__device__ int      g_arrive;
__device__ int      g_exit;

__device__ __forceinline__ unsigned fkey(float f) {
    unsigned b = __float_as_uint(f);
    return (b & 0x80000000u) ? ~b : (b | 0x80000000u);
}
__device__ __forceinline__ float funkey(unsigned k) {
    return __uint_as_float((k & 0x80000000u) ? (k ^ 0x80000000u) : ~k);
}

// 2-column accumulator (register-lean: ~9 regs)
struct Acc2 {
    float sx, sy, qx, qy, mnx, mny, mxx, mxy;
    int cnt;
};
__device__ __forceinline__ void acc_reset(Acc2& a, float2 v) {
    a.sx = v.x; a.sy = v.y;
    a.qx = v.x * v.x; a.qy = v.y * v.y;
    a.mnx = v.x; a.mny = v.y;
    a.mxx = v.x; a.mxy = v.y;
    a.cnt = 1;
}
__device__ __forceinline__ void acc_add(Acc2& a, float2 v) {
    a.sx += v.x; a.sy += v.y;
    a.qx = fmaf(v.x, v.x, a.qx); a.qy = fmaf(v.y, v.y, a.qy);
    a.mnx = fminf(a.mnx, v.x); a.mny = fminf(a.mny, v.y);
    a.mxx = fmaxf(a.mxx, v.x); a.mxy = fmaxf(a.mxy, v.y);
}
__device__ __forceinline__ void acc_flush(const Acc2& a, int seg, int colbase,
                                          bool addCnt) {
    int o = seg * HDIM + colbase;
    atomicAdd(&g_sum[o + 0], a.sx); atomicAdd(&g_sum[o + 1], a.sy);
    atomicAdd(&g_sq [o + 0], a.qx); atomicAdd(&g_sq [o + 1], a.qy);
    atomicMax(&g_minb[o + 0], fkey(-a.mnx));
    atomicMax(&g_minb[o + 1], fkey(-a.mny));
    atomicMax(&g_maxb[o + 0], fkey(a.mxx));
    atomicMax(&g_maxb[o + 1], fkey(a.mxy));
    if (addCnt) atomicAdd(&g_cnt[seg], (float)a.cnt);
}

// smem union: phase-1 segment buffer overlays the MLP staging buffers
struct MlpS {
    float concat[2][5 * HDIM];   // 5 KB
    float part0[16][2][MH];      // 8 KB
    float part1[4][2][MH];       // 2 KB
    float part3[2][2][HDIM];     // 2 KB
    float h0[2][MH];
    float hb[2][MH];
};
union SmemU {
    int sb[CHUNK];
    MlpS m;
};

__global__ void __launch_bounds__(256, 6) fused_kernel(
    const float2* __restrict__ x2, const int* __restrict__ batch,
    int N, int nChunks, int NB,
    const float* __restrict__ u,
    const float* __restrict__ W0, const float* __restrict__ b0,
    const float* __restrict__ W1, const float* __restrict__ b1,
    const float* __restrict__ W2, const float* __restrict__ b2,
    const float* __restrict__ lng, const float* __restrict__ lnb,
    const float* __restrict__ W3, const float* __restrict__ b3,
    float* __restrict__ out, int B) {
    __shared__ SmemU s;
    const int t = threadIdx.x;
    const int warp = t >> 5;
    const int lane = t & 31;

    // ================= phase 1: chunks strided over persistent blocks ======
    // warp-pair (warp>>1) owns a 256-row range; (warp&1) selects column half.
    const int pair = warp >> 1;
    const int half = warp & 1;
    const int colbase = half * 64 + lane * 2;
    const bool cntOwner = (lane == 0) && (half == 0);

    for (int chunk = blockIdx.x; chunk < nChunks; chunk += NB) {
        const long long chunkStart = (long long)chunk * CHUNK;
        const int rows = (int)min((long long)CHUNK, (long long)N - chunkStart);

        for (int i = t; i < rows; i += 256) s.sb[i] = batch[chunkStart + i];
        __syncthreads();

        const int wstart = pair * ROWS_PER_PAIR;
        if (wstart < rows) {
            const int wend = min(wstart + ROWS_PER_PAIR, rows);
            const float2* xp = x2 + (chunkStart + wstart) * (HDIM / 2)
                                  + (colbase >> 1);

            Acc2 a;
            int cur = s.sb[wstart];
            {
                float2 v0 = __ldcs(xp);
                acc_reset(a, v0);
                xp += HDIM / 2;
            }
            int i = wstart + 1;
            for (; i + 8 <= wend; i += 8) {
                float2 v[8];
#pragma unroll
                for (int j = 0; j < 8; ++j) v[j] = __ldcs(xp + j * (HDIM / 2));
                if (s.sb[i + 7] == cur) {
#pragma unroll
                    for (int j = 0; j < 8; ++j) acc_add(a, v[j]);
                    a.cnt += 8;
                } else {
#pragma unroll
                    for (int j = 0; j < 8; ++j) {
                        int sg = s.sb[i + j];
                        if (sg != cur) {
                            acc_flush(a, cur, colbase, cntOwner);
                            cur = sg;
                            acc_reset(a, v[j]);
                        } else {
                            acc_add(a, v[j]);
                            a.cnt++;
                        }
                    }
                }
                xp += 8 * (HDIM / 2);
            }
            for (; i < wend; ++i) {
                float2 v = __ldcs(xp);
                int sg = s.sb[i];
                if (sg != cur) {
                    acc_flush(a, cur, colbase, cntOwner);
                    cur = sg;
                    acc_reset(a, v);
                } else {
                    acc_add(a, v);
                    a.cnt++;
                }
                xp += HDIM / 2;
            }
            acc_flush(a, cur, colbase, cntOwner);
        }
        __syncthreads();   // protect s.sb before next chunk load
    }

    // ================= grid-wide barrier (all NB blocks co-resident) =======
    __threadfence();
    __syncthreads();
    if (t == 0) {
        atomicAdd(&g_arrive, 1);
        while (*(volatile int*)&g_arrive < NB) { __nanosleep(64); }
    }
    __syncthreads();
    __threadfence();

    // ================= MLP tail: 2 graphs per block =========================
    const int PAIRS = (B + 1) / 2;
    for (int p = blockIdx.x; p < PAIRS; p += NB) {
        const int g0 = p * 2;
        const int g1 = (p * 2 + 1 < B) ? p * 2 + 1 : p * 2;

        // ---- build concat = [u, s, min, max, var] for both graphs ----
        for (int idx = t; idx < 2 * 5 * HDIM; idx += 256) {
            int g = idx / (5 * HDIM);
            int j = idx - g * (5 * HDIM);
            int gid = g ? g1 : g0;
            int o = gid * HDIM + (j & (HDIM - 1));
            int sec = j >> 7;
            float val;
            if (sec == 0) {
                val = u[o];
            } else if (sec == 1) {
                val = g_sum[o];
            } else if (sec == 2) {
                val = -funkey(g_minb[o]);
            } else if (sec == 3) {
                val = funkey(g_maxb[o]);
            } else {
                float cv = fmaxf(g_cnt[gid], 1.0f);
                float me = g_sum[o] / cv;
                val = g_sq[o] / cv - me * me;
            }
            s.m.concat[g][j] = val;
        }
        __syncthreads();

        // ---- layer 0: 640 -> 64; 16-way K-split, 4 out x 2 graphs ----
        {
            const int mg = (t & 15) * 4;
            const int q  = t >> 4;
            float a00 = 0.f, a01 = 0.f, a02 = 0.f, a03 = 0.f;
            float a10 = 0.f, a11 = 0.f, a12 = 0.f, a13 = 0.f;
            const int k0 = q * 40;
#pragma unroll 8
            for (int k = k0; k < k0 + 40; ++k) {
                float4 w = *(const float4*)&W0[k * MH + mg];
                float c0 = s.m.concat[0][k];
                float c1 = s.m.concat[1][k];
                a00 = fmaf(c0, w.x, a00); a01 = fmaf(c0, w.y, a01);
                a02 = fmaf(c0, w.z, a02); a03 = fmaf(c0, w.w, a03);
                a10 = fmaf(c1, w.x, a10); a11 = fmaf(c1, w.y, a11);
                a12 = fmaf(c1, w.z, a12); a13 = fmaf(c1, w.w, a13);
            }
            s.m.part0[q][0][mg + 0] = a00; s.m.part0[q][0][mg + 1] = a01;
            s.m.part0[q][0][mg + 2] = a02; s.m.part0[q][0][mg + 3] = a03;
            s.m.part0[q][1][mg + 0] = a10; s.m.part0[q][1][mg + 1] = a11;
            s.m.part0[q][1][mg + 2] = a12; s.m.part0[q][1][mg + 3] = a13;
        }
        __syncthreads();
        if (t < 2 * MH) {
            int g = t >> 6, m = t & 63;
            float sum = 0.f;
#pragma unroll
            for (int q = 0; q < 16; ++q) sum += s.m.part0[q][g][m];
            s.m.h0[g][m] = fmaxf(sum + b0[m], 0.f);
        }
        __syncthreads();

        // ---- layer 1: 64 -> 64; 4-way K-split x 2 graphs ----
        {
            const int m = t & 63;
            const int q = t >> 6;
            float ac0 = 0.f, ac1 = 0.f;
            const int k0 = q * 16;
#pragma unroll
            for (int k = k0; k < k0 + 16; ++k) {
                float w = __ldg(&W1[k * MH + m]);
                ac0 = fmaf(s.m.h0[0][k], w, ac0);
                ac1 = fmaf(s.m.h0[1][k], w, ac1);
            }
            s.m.part1[q][0][m] = ac0;
            s.m.part1[q][1][m] = ac1;
        }
        __syncthreads();
        if (t < 2 * MH) {
            int g = t >> 6, m = t & 63;
            s.m.hb[g][m] = fmaxf(s.m.part1[0][g][m] + s.m.part1[1][g][m] +
                                 s.m.part1[2][g][m] + s.m.part1[3][g][m] + b1[m], 0.f);
        }
        __syncthreads();

        // ---- layer 2: 64 -> 64; 4-way K-split x 2 graphs ----
        {
            const int m = t & 63;
            const int q = t >> 6;
            float ac0 = 0.f, ac1 = 0.f;
            const int k0 = q * 16;
#pragma unroll
            for (int k = k0; k < k0 + 16; ++k) {
                float w = __ldg(&W2[k * MH + m]);
                ac0 = fmaf(s.m.hb[0][k], w, ac0);
                ac1 = fmaf(s.m.hb[1][k], w, ac1);
            }
            s.m.part1[q][0][m] = ac0;
            s.m.part1[q][1][m] = ac1;
        }
        __syncthreads();
        if (t < 2 * MH) {
            int g = t >> 6, m = t & 63;
            s.m.h0[g][m] = fmaxf(s.m.part1[0][g][m] + s.m.part1[1][g][m] +
                                 s.m.part1[2][g][m] + s.m.part1[3][g][m] + b2[m], 0.f);
        }
        __syncthreads();

        // ---- layernorm: warp g handles graph g ----
        if (t < 64) {
            const int g = t >> 5;
            const int l = t & 31;
            float v0 = s.m.h0[g][l], v1 = s.m.h0[g][l + 32];
            float sum = v0 + v1;
#pragma unroll
            for (int o = 16; o > 0; o >>= 1) sum += __shfl_xor_sync(0xFFFFFFFF, sum, o);
            float mu = sum * (1.0f / MH);
            float d0 = v0 - mu, d1 = v1 - mu;
            float vs = d0 * d0 + d1 * d1;
#pragma unroll
            for (int o = 16; o > 0; o >>= 1) vs += __shfl_xor_sync(0xFFFFFFFF, vs, o);
            float rstd = rsqrtf(vs * (1.0f / MH) + LN_EPS);
            s.m.hb[g][l]      = d0 * rstd * lng[l]      + lnb[l];
            s.m.hb[g][l + 32] = d1 * rstd * lng[l + 32] + lnb[l + 32];
        }
        __syncthreads();

        // ---- output layer: 64 -> 128; 2-way K-split x 2 graphs ----
        {
            const int col = t & 127;
            const int hf  = t >> 7;
            float ac0 = 0.f, ac1 = 0.f;
            const int k0 = hf * 32;
#pragma unroll 8
            for (int k = k0; k < k0 + 32; ++k) {
                float w = __ldg(&W3[k * HDIM + col]);
                ac0 = fmaf(s.m.hb[0][k], w, ac0);
                ac1 = fmaf(s.m.hb[1][k], w, ac1);
            }
            s.m.part3[hf][0][col] = ac0;
            s.m.part3[hf][1][col] = ac1;
        }
        __syncthreads();
        {
            const int g = t >> 7;
            const int col = t & 127;
            const int gid = g ? g1 : g0;
            int o = gid * HDIM + col;
            out[o] = u[o] + b3[col] + s.m.part3[0][g][col] + s.m.part3[1][g][col];

            // reset scratch slice to zero-identity for next replay
            g_sum[o] = 0.f;
            g_sq[o] = 0.f;
            g_minb[o] = 0u;
            g_maxb[o] = 0u;
            if (col == 0) g_cnt[gid] = 0.f;
        }
        __syncthreads();   // protect smem before next pair iteration
    }

    // ================= exit ticket: last block resets barrier counters =====
    __threadfence();
    __syncthreads();
    if (t == 0) {
        int tk = atomicAdd(&g_exit, 1);
        if (tk == NB - 1) {
            g_arrive = 0;
            g_exit = 0;
            __threadfence();
        }
    }
}

// ---------------- launch ----------------
extern "C" void kernel_launch(void* const* d_in, const int* in_sizes, int n_in,
                              void* d_out, int out_size) {
    const float* x     = (const float*)d_in[0];
    // d_in[1] edge_index, d_in[2] edge_attr : unused by the forward
    const float* u     = (const float*)d_in[3];
    const int*   batch = (const int*)d_in[4];
    const float* W0    = (const float*)d_in[5];
    const float* b0    = (const float*)d_in[6];
    const float* W1    = (const float*)d_in[7];
    const float* b1    = (const float*)d_in[8];
    const float* W2    = (const float*)d_in[9];
    const float* b2    = (const float*)d_in[10];
    const float* lng   = (const float*)d_in[11];
    const float* lnb   = (const float*)d_in[12];
    const float* W3    = (const float*)d_in[13];
    const float* b3    = (const float*)d_in[14];
    float* out = (float*)d_out;

    const int N = in_sizes[0] / HDIM;
    int B = in_sizes[3] / HDIM;
    if (B > MAXB) B = MAXB;

    static int smCount = 0;
    if (smCount == 0) {
        cudaDeviceGetAttribute(&smCount, cudaDevAttrMultiProcessorCount, 0);
        if (smCount <= 0) smCount = 148;
    }
    const int NB = smCount * 6;   // __launch_bounds__(256,6) guarantees residency
    const int nChunks = (N + CHUNK - 1) / CHUNK;

    fused_kernel<<<NB, 256>>>((const float2*)x, batch, N, nChunks, NB,
                              u, W0, b0, W1, b1, W2, b2, lng, lnb, W3, b3,
                              out, B);
}

// round 12
// speedup vs baseline: 1.0432x; 1.0097x over previous
#include <cuda_runtime.h>
#include <cuda_bf16.h>
#include <cstdint>

#define HDIM 128
#define MH 64
#define MAXB 2048
#define CHUNK 1024
#define ROWS_PER_PAIR 256
#define LN_EPS 1e-5f

// ---------------- scratch (static device globals; zero-initialized) -------
// ZERO is the identity everywhere (min kept as max of negated keys); the MLP
// tail zeroes each graph's slice after reading, and the exit ticket resets
// the barrier + work counters, so every graph replay sees identity state.
__device__ float    g_sum [MAXB * HDIM];
__device__ float    g_sq  [MAXB * HDIM];
__device__ unsigned g_minb[MAXB * HDIM];   // max of fkey(-v)
__device__ unsigned g_maxb[MAXB * HDIM];   // max of fkey(v)
__device__ float    g_cnt [MAXB];
__device__ int      g_arrive;
__device__ int      g_exit;
__device__ int      g_work1;               // phase-1 chunk counter
__device__ int      g_work2;               // MLP pair counter

__device__ __forceinline__ unsigned fkey(float f) {
    unsigned b = __float_as_uint(f);
    return (b & 0x80000000u) ? ~b : (b | 0x80000000u);
}
__device__ __forceinline__ float funkey(unsigned k) {
    return __uint_as_float((k & 0x80000000u) ? (k ^ 0x80000000u) : ~k);
}

// 2-column accumulator (register-lean)
struct Acc2 {
    float sx, sy, qx, qy, mnx, mny, mxx, mxy;
    int cnt;
};
__device__ __forceinline__ void acc_reset(Acc2& a, float2 v) {
    a.sx = v.x; a.sy = v.y;
    a.qx = v.x * v.x; a.qy = v.y * v.y;
    a.mnx = v.x; a.mny = v.y;
    a.mxx = v.x; a.mxy = v.y;
    a.cnt = 1;
}
__device__ __forceinline__ void acc_add(Acc2& a, float2 v) {
    a.sx += v.x; a.sy += v.y;
    a.qx = fmaf(v.x, v.x, a.qx); a.qy = fmaf(v.y, v.y, a.qy);
    a.mnx = fminf(a.mnx, v.x); a.mny = fminf(a.mny, v.y);
    a.mxx = fmaxf(a.mxx, v.x); a.mxy = fmaxf(a.mxy, v.y);
}
__device__ __forceinline__ void acc_flush(const Acc2& a, int seg, int colbase,
                                          bool addCnt) {
    int o = seg * HDIM + colbase;
    atomicAdd(&g_sum[o + 0], a.sx); atomicAdd(&g_sum[o + 1], a.sy);
    atomicAdd(&g_sq [o + 0], a.qx); atomicAdd(&g_sq [o + 1], a.qy);
    atomicMax(&g_minb[o + 0], fkey(-a.mnx));
    atomicMax(&g_minb[o + 1], fkey(-a.mny));
    atomicMax(&g_maxb[o + 0], fkey(a.mxx));
    atomicMax(&g_maxb[o + 1], fkey(a.mxy));
    if (addCnt) atomicAdd(&g_cnt[seg], (float)a.cnt);
}

// smem union: phase-1 segment buffer overlays the MLP staging buffers
struct MlpS {
    float concat[2][5 * HDIM];   // 5 KB
    float part0[16][2][MH];      // 8 KB
    float part1[4][2][MH];       // 2 KB
    float part3[2][2][HDIM];     // 2 KB
    float h0[2][MH];
    float hb[2][MH];
};
union SmemU {
    int sb[CHUNK];
    MlpS m;
};

__global__ void __launch_bounds__(256, 6) fused_kernel(
    const float2* __restrict__ x2, const int* __restrict__ batch,
    int N, int nChunks, int NB,
    const float* __restrict__ u,
    const float* __restrict__ W0, const float* __restrict__ b0,
    const float* __restrict__ W1, const float* __restrict__ b1,
    const float* __restrict__ W2, const float* __restrict__ b2,
    const float* __restrict__ lng, const float* __restrict__ lnb,
    const float* __restrict__ W3, const float* __restrict__ b3,
    float* __restrict__ out, int B) {
    __shared__ SmemU s;
    __shared__ int sWork;
    const int t = threadIdx.x;
    const int warp = t >> 5;
    const int lane = t & 31;

    // ============ phase 1: work-stealing chunks (work-conserving) ==========
    const int pair = warp >> 1;               // warp-pair owns 256-row range
    const int half = warp & 1;                // column half
    const int colbase = half * 64 + lane * 2;
    const bool cntOwner = (lane == 0) && (half == 0);

    for (;;) {
        if (t == 0) sWork = atomicAdd(&g_work1, 1);
        __syncthreads();
        const int chunk = sWork;
        if (chunk >= nChunks) break;

        const long long chunkStart = (long long)chunk * CHUNK;
        const int rows = (int)min((long long)CHUNK, (long long)N - chunkStart);

        for (int i = t; i < rows; i += 256) s.sb[i] = batch[chunkStart + i];
        __syncthreads();

        const int wstart = pair * ROWS_PER_PAIR;
        if (wstart < rows) {
            const int wend = min(wstart + ROWS_PER_PAIR, rows);
            const float2* xp = x2 + (chunkStart + wstart) * (HDIM / 2)
                                  + (colbase >> 1);

            Acc2 a;
            int cur = s.sb[wstart];
            {
                float2 v0 = __ldcs(xp);
                acc_reset(a, v0);
                xp += HDIM / 2;
            }
            int i = wstart + 1;
            for (; i + 8 <= wend; i += 8) {
                float2 v[8];
#pragma unroll
                for (int j = 0; j < 8; ++j) v[j] = __ldcs(xp + j * (HDIM / 2));
                if (s.sb[i + 7] == cur) {
#pragma unroll
                    for (int j = 0; j < 8; ++j) acc_add(a, v[j]);
                    a.cnt += 8;
                } else {
#pragma unroll
                    for (int j = 0; j < 8; ++j) {
                        int sg = s.sb[i + j];
                        if (sg != cur) {
                            acc_flush(a, cur, colbase, cntOwner);
                            cur = sg;
                            acc_reset(a, v[j]);
                        } else {
                            acc_add(a, v[j]);
                            a.cnt++;
                        }
                    }
                }
                xp += 8 * (HDIM / 2);
            }
            for (; i < wend; ++i) {
                float2 v = __ldcs(xp);
                int sg = s.sb[i];
                if (sg != cur) {
                    acc_flush(a, cur, colbase, cntOwner);
                    cur = sg;
                    acc_reset(a, v);
                } else {
                    acc_add(a, v);
                    a.cnt++;
                }
                xp += HDIM / 2;
            }
            acc_flush(a, cur, colbase, cntOwner);
        }
        __syncthreads();   // protect s.sb / sWork before next grab
    }

    // ============ grid-wide barrier (all NB blocks co-resident) ============
    __threadfence();
    // (all threads already synced by the uniform break above)
    if (t == 0) {
        atomicAdd(&g_arrive, 1);
        while (*(volatile int*)&g_arrive < NB) { __nanosleep(64); }
    }
    __syncthreads();
    __threadfence();

    // ============ MLP tail: work-stealing pairs of graphs ==================
    const int PAIRS = (B + 1) / 2;
    for (;;) {
        if (t == 0) sWork = atomicAdd(&g_work2, 1);
        __syncthreads();
        const int p = sWork;
        if (p >= PAIRS) break;

        const int g0 = p * 2;
        const int g1 = (p * 2 + 1 < B) ? p * 2 + 1 : p * 2;

        // ---- build concat = [u, s, min, max, var] for both graphs ----
        for (int idx = t; idx < 2 * 5 * HDIM; idx += 256) {
            int g = idx / (5 * HDIM);
            int j = idx - g * (5 * HDIM);
            int gid = g ? g1 : g0;
            int o = gid * HDIM + (j & (HDIM - 1));
            int sec = j >> 7;
            float val;
            if (sec == 0) {
                val = u[o];
            } else if (sec == 1) {
                val = g_sum[o];
            } else if (sec == 2) {
                val = -funkey(g_minb[o]);
            } else if (sec == 3) {
                val = funkey(g_maxb[o]);
            } else {
                float cv = fmaxf(g_cnt[gid], 1.0f);
                float me = g_sum[o] / cv;
                val = g_sq[o] / cv - me * me;
            }
            s.m.concat[g][j] = val;
        }
        __syncthreads();

        // ---- layer 0: 640 -> 64; 16-way K-split, 4 out x 2 graphs ----
        {
            const int mg = (t & 15) * 4;
            const int q  = t >> 4;
            float a00 = 0.f, a01 = 0.f, a02 = 0.f, a03 = 0.f;
            float a10 = 0.f, a11 = 0.f, a12 = 0.f, a13 = 0.f;
            const int k0 = q * 40;
#pragma unroll 8
            for (int k = k0; k < k0 + 40; ++k) {
                float4 w = *(const float4*)&W0[k * MH + mg];
                float c0 = s.m.concat[0][k];
                float c1 = s.m.concat[1][k];
                a00 = fmaf(c0, w.x, a00); a01 = fmaf(c0, w.y, a01);
                a02 = fmaf(c0, w.z, a02); a03 = fmaf(c0, w.w, a03);
                a10 = fmaf(c1, w.x, a10); a11 = fmaf(c1, w.y, a11);
                a12 = fmaf(c1, w.z, a12); a13 = fmaf(c1, w.w, a13);
            }
            s.m.part0[q][0][mg + 0] = a00; s.m.part0[q][0][mg + 1] = a01;
            s.m.part0[q][0][mg + 2] = a02; s.m.part0[q][0][mg + 3] = a03;
            s.m.part0[q][1][mg + 0] = a10; s.m.part0[q][1][mg + 1] = a11;
            s.m.part0[q][1][mg + 2] = a12; s.m.part0[q][1][mg + 3] = a13;
        }
        __syncthreads();
        if (t < 2 * MH) {
            int g = t >> 6, m = t & 63;
            float sum = 0.f;
#pragma unroll
            for (int q = 0; q < 16; ++q) sum += s.m.part0[q][g][m];
            s.m.h0[g][m] = fmaxf(sum + b0[m], 0.f);
        }
        __syncthreads();

        // ---- layer 1: 64 -> 64; 4-way K-split x 2 graphs ----
        {
            const int m = t & 63;
            const int q = t >> 6;
            float ac0 = 0.f, ac1 = 0.f;
            const int k0 = q * 16;
#pragma unroll
            for (int k = k0; k < k0 + 16; ++k) {
                float w = __ldg(&W1[k * MH + m]);
                ac0 = fmaf(s.m.h0[0][k], w, ac0);
                ac1 = fmaf(s.m.h0[1][k], w, ac1);
            }
            s.m.part1[q][0][m] = ac0;
            s.m.part1[q][1][m] = ac1;
        }
        __syncthreads();
        if (t < 2 * MH) {
            int g = t >> 6, m = t & 63;
            s.m.hb[g][m] = fmaxf(s.m.part1[0][g][m] + s.m.part1[1][g][m] +
                                 s.m.part1[2][g][m] + s.m.part1[3][g][m] + b1[m], 0.f);
        }
        __syncthreads();

        // ---- layer 2: 64 -> 64; 4-way K-split x 2 graphs ----
        {
            const int m = t & 63;
            const int q = t >> 6;
            float ac0 = 0.f, ac1 = 0.f;
            const int k0 = q * 16;
#pragma unroll
            for (int k = k0; k < k0 + 16; ++k) {
                float w = __ldg(&W2[k * MH + m]);
                ac0 = fmaf(s.m.hb[0][k], w, ac0);
                ac1 = fmaf(s.m.hb[1][k], w, ac1);
            }
            s.m.part1[q][0][m] = ac0;
            s.m.part1[q][1][m] = ac1;
        }
        __syncthreads();
        if (t < 2 * MH) {
            int g = t >> 6, m = t & 63;
            s.m.h0[g][m] = fmaxf(s.m.part1[0][g][m] + s.m.part1[1][g][m] +
                                 s.m.part1[2][g][m] + s.m.part1[3][g][m] + b2[m], 0.f);
        }
        __syncthreads();

        // ---- layernorm: warp g handles graph g ----
        if (t < 64) {
            const int g = t >> 5;
            const int l = t & 31;
            float v0 = s.m.h0[g][l], v1 = s.m.h0[g][l + 32];
            float sum = v0 + v1;
#pragma unroll
            for (int o = 16; o > 0; o >>= 1) sum += __shfl_xor_sync(0xFFFFFFFF, sum, o);
            float mu = sum * (1.0f / MH);
            float d0 = v0 - mu, d1 = v1 - mu;
            float vs = d0 * d0 + d1 * d1;
#pragma unroll
            for (int o = 16; o > 0; o >>= 1) vs += __shfl_xor_sync(0xFFFFFFFF, vs, o);
            float rstd = rsqrtf(vs * (1.0f / MH) + LN_EPS);
            s.m.hb[g][l]      = d0 * rstd * lng[l]      + lnb[l];
            s.m.hb[g][l + 32] = d1 * rstd * lng[l + 32] + lnb[l + 32];
        }
        __syncthreads();

        // ---- output layer: 64 -> 128; 2-way K-split x 2 graphs ----
        {
            const int col = t & 127;
            const int hf  = t >> 7;
            float ac0 = 0.f, ac1 = 0.f;
            const int k0 = hf * 32;
#pragma unroll 8
            for (int k = k0; k < k0 + 32; ++k) {
                float w = __ldg(&W3[k * HDIM + col]);
                ac0 = fmaf(s.m.hb[0][k], w, ac0);
                ac1 = fmaf(s.m.hb[1][k], w, ac1);
            }
            s.m.part3[hf][0][col] = ac0;
            s.m.part3[hf][1][col] = ac1;
        }
        __syncthreads();
        {
            const int g = t >> 7;
            const int col = t & 127;
            const int gid = g ? g1 : g0;
            int o = gid * HDIM + col;
            out[o] = u[o] + b3[col] + s.m.part3[0][g][col] + s.m.part3[1][g][col];

            // reset scratch slice to zero-identity for next replay
            g_sum[o] = 0.f;
            g_sq[o] = 0.f;
            g_minb[o] = 0u;
            g_maxb[o] = 0u;
            if (col == 0) g_cnt[gid] = 0.f;
        }
        __syncthreads();   // protect smem / sWork before next grab
    }

    // ============ exit ticket: last block resets all counters ==============
    __threadfence();
    if (t == 0) {
        int tk = atomicAdd(&g_exit, 1);
        if (tk == NB - 1) {
            g_arrive = 0;
            g_exit = 0;
            g_work1 = 0;
            g_work2 = 0;
            __threadfence();
        }
    }
}

// ---------------- launch ----------------
extern "C" void kernel_launch(void* const* d_in, const int* in_sizes, int n_in,
                              void* d_out, int out_size) {
    const float* x     = (const float*)d_in[0];
    // d_in[1] edge_index, d_in[2] edge_attr : unused by the forward
    const float* u     = (const float*)d_in[3];
    const int*   batch = (const int*)d_in[4];
    const float* W0    = (const float*)d_in[5];
    const float* b0    = (const float*)d_in[6];
    const float* W1    = (const float*)d_in[7];
    const float* b1    = (const float*)d_in[8];
    const float* W2    = (const float*)d_in[9];
    const float* b2    = (const float*)d_in[10];
    const float* lng   = (const float*)d_in[11];
    const float* lnb   = (const float*)d_in[12];
    const float* W3    = (const float*)d_in[13];
    const float* b3    = (const float*)d_in[14];
    float* out = (float*)d_out;

    const int N = in_sizes[0] / HDIM;
    int B = in_sizes[3] / HDIM;
    if (B > MAXB) B = MAXB;

    static int smCount = 0;
    if (smCount == 0) {
        cudaDeviceGetAttribute(&smCount, cudaDevAttrMultiProcessorCount, 0);
        if (smCount <= 0) smCount = 148;
    }
    const int NB = smCount * 6;   // __launch_bounds__(256,6) guarantees residency
    const int nChunks = (N + CHUNK - 1) / CHUNK;

    fused_kernel<<<NB, 256>>>((const float2*)x, batch, N, nChunks, NB,
                              u, W0, b0, W1, b1, W2, b2, lng, lnb, W3, b3,
                              out, B);
}

// round 14
// speedup vs baseline: 1.1925x; 1.1431x over previous
#include <cuda_runtime.h>
#include <cuda_bf16.h>
#include <cstdint>

#define HDIM 128
#define MH 64
#define LN_EPS 1e-5f

// ===== single fused kernel: one block per graph =====
// batch is sorted, so graph b's rows are the contiguous range
// [lower_bound(b), lower_bound(b+1)). Each block finds its range by binary
// search, streams it with register-resident per-column stats (no atomics,
// no scratch, no barrier), then runs the MLP for its graph.

__global__ void __launch_bounds__(256, 7) fused_one(
    const float* __restrict__ x, const int* __restrict__ batch, int N,
    const float* __restrict__ u,
    const float* __restrict__ W0, const float* __restrict__ b0,
    const float* __restrict__ W1, const float* __restrict__ b1,
    const float* __restrict__ W2, const float* __restrict__ b2,
    const float* __restrict__ lng, const float* __restrict__ lnb,
    const float* __restrict__ W3, const float* __restrict__ b3,
    float* __restrict__ out) {
    const int b = blockIdx.x;        // graph id
    const int t = threadIdx.x;

    __shared__ int bounds[2];
    __shared__ float red[3][4][HDIM];     // 6 KB: groups 1..3 publish stats
    __shared__ float concat[5 * HDIM];    // 2.5 KB
    __shared__ float part0[16][MH + 1];   // 4.2 KB (padded)
    __shared__ float part1[4][MH + 1];    // 1 KB
    __shared__ float part3[2][HDIM];      // 1 KB
    __shared__ float h0[MH];
    __shared__ float hb[MH];

    // ---- bounds: threads 0,1 binary-search lower_bound(b), lower_bound(b+1)
    if (t < 2) {
        int target = b + t;
        int lo = 0, hi = N;
        while (lo < hi) {
            int mid = (lo + hi) >> 1;
            if (__ldg(&batch[mid]) < target) lo = mid + 1;
            else hi = mid;
        }
        bounds[t] = lo;
    }
    __syncthreads();
    const int lo = bounds[0], hi = bounds[1];
    const int cnt = hi - lo;

    // ---- stream the segment: 4 row-groups of 64 threads; thread covers
    //      cols [2*cp, 2*cp+1] via float2; rows lo+grp, stride 4.
    const int cp  = t & 63;          // column pair
    const int grp = t >> 6;          // 0..3
    float sx = 0.f, sy = 0.f, qx = 0.f, qy = 0.f;
    float mnx = __int_as_float(0x7F800000), mny = mnx;   // +inf
    float mxx = __int_as_float(0xFF800000), mxy = mxx;   // -inf

    int r = lo + grp;
    const float2* xp = (const float2*)x + (long long)r * (HDIM / 2) + cp;
    for (; r + 28 < hi; r += 32) {   // 8 rows per group per iter (stride 4)
        float2 v[8];
#pragma unroll
        for (int j = 0; j < 8; ++j) v[j] = __ldcs(xp + j * 4 * (HDIM / 2));
#pragma unroll
        for (int j = 0; j < 8; ++j) {
            float ax = v[j].x, ay = v[j].y;
            sx += ax; sy += ay;
            qx = fmaf(ax, ax, qx); qy = fmaf(ay, ay, qy);
            mnx = fminf(mnx, ax); mny = fminf(mny, ay);
            mxx = fmaxf(mxx, ax); mxy = fmaxf(mxy, ay);
        }
        xp += 32 * (HDIM / 2);
    }
    for (; r < hi; r += 4) {
        float2 v = __ldcs(xp);
        sx += v.x; sy += v.y;
        qx = fmaf(v.x, v.x, qx); qy = fmaf(v.y, v.y, qy);
        mnx = fminf(mnx, v.x); mny = fminf(mny, v.y);
        mxx = fmaxf(mxx, v.x); mxy = fmaxf(mxy, v.y);
        xp += 4 * (HDIM / 2);
    }

    // ---- cross-group combine (groups 1..3 publish, group 0 merges) ----
    if (grp > 0) {
        red[grp - 1][0][2 * cp] = sx;  red[grp - 1][0][2 * cp + 1] = sy;
        red[grp - 1][1][2 * cp] = qx;  red[grp - 1][1][2 * cp + 1] = qy;
        red[grp - 1][2][2 * cp] = mnx; red[grp - 1][2][2 * cp + 1] = mny;
        red[grp - 1][3][2 * cp] = mxx; red[grp - 1][3][2 * cp + 1] = mxy;
    }
    __syncthreads();
    if (grp == 0) {
#pragma unroll
        for (int g = 0; g < 3; ++g) {
            sx += red[g][0][2 * cp];  sy += red[g][0][2 * cp + 1];
            qx += red[g][1][2 * cp];  qy += red[g][1][2 * cp + 1];
            mnx = fminf(mnx, red[g][2][2 * cp]);
            mny = fminf(mny, red[g][2][2 * cp + 1]);
            mxx = fmaxf(mxx, red[g][3][2 * cp]);
            mxy = fmaxf(mxy, red[g][3][2 * cp + 1]);
        }
        float cv = fmaxf((float)cnt, 1.0f);
        float mex = sx / cv, mey = sy / cv;
        float2 u2 = ((const float2*)u)[b * (HDIM / 2) + cp];
        int c0 = 2 * cp, c1 = 2 * cp + 1;
        concat[c0]            = u2.x;          concat[c1]            = u2.y;
        concat[HDIM + c0]     = sx;            concat[HDIM + c1]     = sy;
        concat[2 * HDIM + c0] = mnx;           concat[2 * HDIM + c1] = mny;
        concat[3 * HDIM + c0] = mxx;           concat[3 * HDIM + c1] = mxy;
        concat[4 * HDIM + c0] = qx / cv - mex * mex;
        concat[4 * HDIM + c1] = qy / cv - mey * mey;
    }
    __syncthreads();

    // ================= MLP (R7-proven structure, single graph) =============
    // layer 0: 640 -> 64; 16-way K-split, 4 outputs/thread via float4
    {
        const int mg = (t & 15) * 4;
        const int q  = t >> 4;           // 0..15
        float a0 = 0.f, a1 = 0.f, a2 = 0.f, a3 = 0.f;
        const int k0 = q * 40;
#pragma unroll 8
        for (int k = k0; k < k0 + 40; ++k) {
            float c = concat[k];
            float4 w = *(const float4*)&W0[k * MH + mg];
            a0 = fmaf(c, w.x, a0);
            a1 = fmaf(c, w.y, a1);
            a2 = fmaf(c, w.z, a2);
            a3 = fmaf(c, w.w, a3);
        }
        part0[q][mg + 0] = a0;
        part0[q][mg + 1] = a1;
        part0[q][mg + 2] = a2;
        part0[q][mg + 3] = a3;
    }
    __syncthreads();
    if (t < MH) {
        float s = 0.f;
#pragma unroll
        for (int q = 0; q < 16; ++q) s += part0[q][t];
        h0[t] = fmaxf(s + b0[t], 0.f);
    }
    __syncthreads();

    // layer 1: 64 -> 64; 4-way K-split
    {
        const int m = t & 63;
        const int q = t >> 6;
        float acc = 0.f;
        const int k0 = q * 16;
#pragma unroll
        for (int k = k0; k < k0 + 16; ++k)
            acc = fmaf(h0[k], __ldg(&W1[k * MH + m]), acc);
        part1[q][m] = acc;
    }
    __syncthreads();
    if (t < MH)
        hb[t] = fmaxf(part1[0][t] + part1[1][t] + part1[2][t] + part1[3][t] + b1[t], 0.f);
    __syncthreads();

    // layer 2: 64 -> 64; 4-way K-split
    {
        const int m = t & 63;
        const int q = t >> 6;
        float acc = 0.f;
        const int k0 = q * 16;
#pragma unroll
        for (int k = k0; k < k0 + 16; ++k)
            acc = fmaf(hb[k], __ldg(&W2[k * MH + m]), acc);
        part1[q][m] = acc;
    }
    __syncthreads();
    if (t < MH)
        h0[t] = fmaxf(part1[0][t] + part1[1][t] + part1[2][t] + part1[3][t] + b2[t], 0.f);
    __syncthreads();

    // layernorm over 64 features (warp 0, shuffle reduce)
    if (t < 32) {
        float v0 = h0[t], v1 = h0[t + 32];
        float s = v0 + v1;
#pragma unroll
        for (int o = 16; o > 0; o >>= 1) s += __shfl_xor_sync(0xFFFFFFFF, s, o);
        float mu = s * (1.0f / MH);
        float d0 = v0 - mu, d1 = v1 - mu;
        float vs = d0 * d0 + d1 * d1;
#pragma unroll
        for (int o = 16; o > 0; o >>= 1) vs += __shfl_xor_sync(0xFFFFFFFF, vs, o);
        float rstd = rsqrtf(vs * (1.0f / MH) + LN_EPS);
        hb[t]      = d0 * rstd * lng[t]      + lnb[t];
        hb[t + 32] = d1 * rstd * lng[t + 32] + lnb[t + 32];
    }
    __syncthreads();

    // output layer: 64 -> 128 + residual; 2-way K-split
    {
        const int col = t & 127;
        const int hf  = t >> 7;
        float acc = 0.f;
        const int k0 = hf * 32;
#pragma unroll 8
        for (int k = k0; k < k0 + 32; ++k)
            acc = fmaf(hb[k], __ldg(&W3[k * HDIM + col]), acc);
        part3[hf][col] = acc;
    }
    __syncthreads();
    if (t < HDIM) {
        int o = b * HDIM + t;
        out[o] = u[o] + b3[t] + part3[0][t] + part3[1][t];
    }
}

// ---------------- launch ----------------
extern "C" void kernel_launch(void* const* d_in, const int* in_sizes, int n_in,
                              void* d_out, int out_size) {
    const float* x     = (const float*)d_in[0];
    // d_in[1] edge_index, d_in[2] edge_attr : unused by the forward
    const float* u     = (const float*)d_in[3];
    const int*   batch = (const int*)d_in[4];
    const float* W0    = (const float*)d_in[5];
    const float* b0    = (const float*)d_in[6];
    const float* W1    = (const float*)d_in[7];
    const float* b1    = (const float*)d_in[8];
    const float* W2    = (const float*)d_in[9];
    const float* b2    = (const float*)d_in[10];
    const float* lng   = (const float*)d_in[11];
    const float* lnb   = (const float*)d_in[12];
    const float* W3    = (const float*)d_in[13];
    const float* b3    = (const float*)d_in[14];
    float* out = (float*)d_out;

    const int N = in_sizes[0] / HDIM;
    const int B = in_sizes[3] / HDIM;

    fused_one<<<B, 256>>>(x, batch, N, u, W0, b0, W1, b1, W2, b2,
                          lng, lnb, W3, b3, out);
}